// round 8
// baseline (speedup 1.0000x reference)
#include <cuda_runtime.h>
#include <cstdint>

#define BB 4
#define CC 192
#define NN 4096
#define KK 9

__device__ __align__(256) float g_xn[(size_t)BB * CC * NN];   // normalized pts [b][c][n]
__device__ __align__(256) float g_sq[(size_t)BB * NN];        // per-point sum of squares
__device__ __align__(256) float g_dist[(size_t)BB * NN * NN]; // distance matrix

// ---------------------------------------------------------------------------
// Kernel 1: L2-normalize over channel dim. x layout [B][C][N], N = H*W.
// ---------------------------------------------------------------------------
__global__ void normalize_kernel(const float* __restrict__ x) {
    int b = blockIdx.y;
    int n = blockIdx.x * blockDim.x + threadIdx.x;
    if (n >= NN) return;
    const float* xb = x + (size_t)b * CC * NN + n;
    float s = 0.f;
    for (int c = 0; c < CC; c++) { float v = xb[(size_t)c * NN]; s += v * v; }
    float denom = fmaxf(sqrtf(s), 1e-12f);
    float* xnb = g_xn + (size_t)b * CC * NN + n;
    float sq = 0.f;
    for (int c = 0; c < CC; c++) {
        float p = xb[(size_t)c * NN] / denom;
        xnb[(size_t)c * NN] = p;
        sq += p * p;
    }
    g_sq[(size_t)b * NN + n] = sq;
}

// ---------------------------------------------------------------------------
// Kernel 2: dist[b][n][m] = (sq[n] + (-2*dot(n,m))) + sq[m]
// 128x128 block tile, TK=16, 8x8 per thread.
// ---------------------------------------------------------------------------
__global__ __launch_bounds__(256) void dist_gemm_kernel() {
    __shared__ float As[16][128];
    __shared__ float Bs[16][128];
    const int b  = blockIdx.z;
    const int n0 = blockIdx.y * 128;
    const int m0 = blockIdx.x * 128;
    const float* base = g_xn + (size_t)b * CC * NN;
    const int tid = threadIdx.x;
    const int tx = tid & 15;
    const int ty = tid >> 4;

    float acc[8][8];
    #pragma unroll
    for (int i = 0; i < 8; i++)
        #pragma unroll
        for (int j = 0; j < 8; j++) acc[i][j] = 0.f;

    for (int c0 = 0; c0 < CC; c0 += 16) {
        for (int idx = tid; idx < 16 * 128; idx += 256) {
            int kk  = idx >> 7;
            int col = idx & 127;
            const float* src = base + (size_t)(c0 + kk) * NN;
            As[kk][col] = src[n0 + col];
            Bs[kk][col] = src[m0 + col];
        }
        __syncthreads();
        #pragma unroll
        for (int kk = 0; kk < 16; kk++) {
            float a[8], bv[8];
            #pragma unroll
            for (int i = 0; i < 8; i++) a[i]  = As[kk][ty * 8 + i];
            #pragma unroll
            for (int j = 0; j < 8; j++) bv[j] = Bs[kk][tx * 8 + j];
            #pragma unroll
            for (int i = 0; i < 8; i++)
                #pragma unroll
                for (int j = 0; j < 8; j++)
                    acc[i][j] += a[i] * bv[j];
        }
        __syncthreads();
    }

    const float* sqb = g_sq + (size_t)b * NN;
    float sqm[8];
    #pragma unroll
    for (int j = 0; j < 8; j++) sqm[j] = sqb[m0 + tx * 8 + j];
    #pragma unroll
    for (int i = 0; i < 8; i++) {
        int n = n0 + ty * 8 + i;
        float sqn = sqb[n];
        float* drow = g_dist + ((size_t)b * NN + n) * NN + m0 + tx * 8;
        #pragma unroll
        for (int j = 0; j < 8; j++)
            drow[j] = (sqn + (-2.0f * acc[i][j])) + sqm[j];
    }
}

// ---------------------------------------------------------------------------
// Kernel 3: warp-per-row top-10 ascending (dist, idx); drop rank 0 (self).
// Output written as FLOAT (harness __output__ dtype is float32).
// ---------------------------------------------------------------------------
__device__ __forceinline__ unsigned ford(float f) {
    unsigned u = __float_as_uint(f);
    return (u & 0x80000000u) ? ~u : (u | 0x80000000u);
}

__global__ void select_topk_kernel(float* __restrict__ out) {
    const int warp = (blockIdx.x * blockDim.x + threadIdx.x) >> 5;
    const int lane = threadIdx.x & 31;
    if (warp >= BB * NN) return;
    const int row = warp;
    const int b = row >> 12;
    const int n = row & (NN - 1);
    const float* drow = g_dist + (size_t)row * NN;

    float v[10]; int id[10];
    #pragma unroll
    for (int k = 0; k < 10; k++) { v[k] = 3.4e38f; id[k] = 0x7FFFFFFF; }

    for (int m = lane; m < NN; m += 32) {
        float val = drow[m];
        if ((val < v[9]) || (val == v[9] && m < id[9])) {
            v[9] = val; id[9] = m;
            #pragma unroll
            for (int k = 9; k > 0; k--) {
                bool sw = (v[k] < v[k-1]) || (v[k] == v[k-1] && id[k] < id[k-1]);
                if (sw) {
                    float tv = v[k]; v[k] = v[k-1]; v[k-1] = tv;
                    int ti = id[k]; id[k] = id[k-1]; id[k-1] = ti;
                }
            }
        }
    }

    const size_t L = (size_t)BB * NN * KK;
    const size_t outbase = (size_t)row * KK;
    int pos = 0;
    for (int k = 0; k < 10; k++) {
        unsigned long long myk = (pos < 10)
            ? (((unsigned long long)ford(v[pos]) << 32) | (unsigned)id[pos])
            : 0xFFFFFFFFFFFFFFFFULL;
        unsigned long long mn = myk;
        #pragma unroll
        for (int off = 16; off > 0; off >>= 1) {
            unsigned long long o = __shfl_xor_sync(0xFFFFFFFFu, mn, off);
            mn = (o < mn) ? o : mn;
        }
        if (myk == mn) pos++;
        if (k > 0 && lane == 0)
            out[outbase + (k - 1)] = (float)((int)(mn & 0xFFFFFFFFu) + b * NN);
    }
    if (lane < KK) out[L + outbase + lane] = (float)(n + b * NN);
}

// ---------------------------------------------------------------------------
extern "C" void kernel_launch(void* const* d_in, const int* in_sizes, int n_in,
                              void* d_out, int out_size) {
    const float* x = (const float*)d_in[0];
    float* out = (float*)d_out;

    { dim3 grid(NN / 256, BB); normalize_kernel<<<grid, 256>>>(x); }
    { dim3 grid(NN / 128, NN / 128, BB); dist_gemm_kernel<<<grid, 256>>>(); }
    { int rows = BB * NN; select_topk_kernel<<<(rows * 32 + 255) / 256, 256>>>(out); }
}